// round 2
// baseline (speedup 1.0000x reference)
#include <cuda_runtime.h>

// Problem constants
#define SEQ 128
#define BATCH 8192
#define EMB 300
#define FEAT (2*EMB)      // 600
#define H1DIM 2048
#define H2DIM 2048
#define NCLASS 1221
#define PAD_ID 1

// Scratch (static device globals: allowed; no runtime allocation)
__device__ float g_feat[(size_t)BATCH * FEAT];
__device__ float g_h1[(size_t)BATCH * H1DIM];
__device__ float g_h2[(size_t)BATCH * H2DIM];

// ---------------------------------------------------------------------------
// Stage 1: features. One block per sentence.
//  feat[b, 0:300]   = emb[x[0,b]]            (first-token embedding)
//  feat[b, 300:600] = mean_{s<=last} emb[x[s,b]]
// last = index of last non-PAD token (S-1 if none).
// ---------------------------------------------------------------------------
__global__ __launch_bounds__(320) void feat_kernel(const int* __restrict__ x,
                                                   const float* __restrict__ emb,
                                                   float* __restrict__ feat) {
    __shared__ int toks[SEQ];
    __shared__ int s_last;
    const int b = blockIdx.x;
    const int tid = threadIdx.x;

    if (tid < SEQ) toks[tid] = x[(size_t)tid * BATCH + b];   // x is [S, B]
    __syncthreads();

    if (tid == 0) {
        int last = SEQ - 1;
        for (int s = SEQ - 1; s >= 0; --s) {
            if (toks[s] != PAD_ID) { last = s; break; }
        }
        s_last = last;
    }
    __syncthreads();

    const int last = s_last;
    const float inv = 1.0f / (float)(last + 1);

    const int e = tid;
    if (e < EMB) {
        float acc = 0.0f;
        int s = 0;
        // unroll by 4 for memory-level parallelism
        for (; s + 3 <= last; s += 4) {
            float v0 = emb[(size_t)toks[s + 0] * EMB + e];
            float v1 = emb[(size_t)toks[s + 1] * EMB + e];
            float v2 = emb[(size_t)toks[s + 2] * EMB + e];
            float v3 = emb[(size_t)toks[s + 3] * EMB + e];
            acc += (v0 + v1) + (v2 + v3);
        }
        for (; s <= last; ++s) acc += emb[(size_t)toks[s] * EMB + e];

        feat[(size_t)b * FEAT + e]       = emb[(size_t)toks[0] * EMB + e];
        feat[(size_t)b * FEAT + EMB + e] = acc * inv;
    }
}

// ---------------------------------------------------------------------------
// Stage 2: NT SGEMM with fused bias + optional ReLU.
//   C[m,n] = act( sum_k A[m,k] * B[n,k] + bias[n] )
// A: [M,K] row-major, B: [N,K] row-major (i.e. C = A @ B^T), C: [M,N].
// 128x128 block tile, BK=16, 256 threads, 8x8 per-thread micro-tile.
// Requires K % 4 == 0 (true: 600, 2048). M % 128 == 0 (true: 8192).
// N guarded (1221 case).
// ---------------------------------------------------------------------------
__global__ __launch_bounds__(256) void sgemm_nt_bias_act(
        const float* __restrict__ A, const float* __restrict__ B,
        const float* __restrict__ bias, float* __restrict__ C,
        int M, int N, int K, int relu) {
    const int BM = 128, BN = 128, BK = 16;
    __shared__ float As[BK][BM];
    __shared__ float Bs[BK][BN];

    const int tid = threadIdx.x;
    const int tx = tid & 15;          // 0..15 -> column group
    const int ty = tid >> 4;          // 0..15 -> row group
    const int bm = blockIdx.y * BM;
    const int bn = blockIdx.x * BN;

    float acc[8][8];
#pragma unroll
    for (int i = 0; i < 8; ++i)
#pragma unroll
        for (int j = 0; j < 8; ++j) acc[i][j] = 0.0f;

    for (int k0 = 0; k0 < K; k0 += BK) {
        // Load A tile (128 rows x 16 cols) as float4, store transposed.
#pragma unroll
        for (int i = 0; i < 2; ++i) {
            int idx = tid + i * 256;        // 0..511
            int row = idx >> 2;             // 0..127
            int c4  = (idx & 3) * 4;        // 0,4,8,12
            int gk  = k0 + c4;
            float4 v = make_float4(0.f, 0.f, 0.f, 0.f);
            if (gk < K) // K % 4 == 0 -> whole float4 in range
                v = *reinterpret_cast<const float4*>(&A[(size_t)(bm + row) * K + gk]);
            As[c4 + 0][row] = v.x; As[c4 + 1][row] = v.y;
            As[c4 + 2][row] = v.z; As[c4 + 3][row] = v.w;
        }
        // Load B tile (128 n-rows x 16 k-cols), transposed, with N guard.
#pragma unroll
        for (int i = 0; i < 2; ++i) {
            int idx = tid + i * 256;
            int row = idx >> 2;
            int c4  = (idx & 3) * 4;
            int gk  = k0 + c4;
            int gn  = bn + row;
            float4 v = make_float4(0.f, 0.f, 0.f, 0.f);
            if (gk < K && gn < N)
                v = *reinterpret_cast<const float4*>(&B[(size_t)gn * K + gk]);
            Bs[c4 + 0][row] = v.x; Bs[c4 + 1][row] = v.y;
            Bs[c4 + 2][row] = v.z; Bs[c4 + 3][row] = v.w;
        }
        __syncthreads();

#pragma unroll
        for (int k = 0; k < BK; ++k) {
            float4 a0 = *reinterpret_cast<const float4*>(&As[k][ty * 8]);
            float4 a1 = *reinterpret_cast<const float4*>(&As[k][ty * 8 + 4]);
            float4 b0 = *reinterpret_cast<const float4*>(&Bs[k][tx * 8]);
            float4 b1 = *reinterpret_cast<const float4*>(&Bs[k][tx * 8 + 4]);
            float ar[8] = {a0.x, a0.y, a0.z, a0.w, a1.x, a1.y, a1.z, a1.w};
            float br[8] = {b0.x, b0.y, b0.z, b0.w, b1.x, b1.y, b1.z, b1.w};
#pragma unroll
            for (int i = 0; i < 8; ++i)
#pragma unroll
                for (int j = 0; j < 8; ++j)
                    acc[i][j] = fmaf(ar[i], br[j], acc[i][j]);
        }
        __syncthreads();
    }

    // Epilogue: bias + activation + guarded store.
    float bs[8];
#pragma unroll
    for (int j = 0; j < 8; ++j) {
        int gn = bn + tx * 8 + j;
        bs[j] = (gn < N) ? bias[gn] : 0.0f;
    }
#pragma unroll
    for (int i = 0; i < 8; ++i) {
        int gm = bm + ty * 8 + i;
        if (gm >= M) continue;
#pragma unroll
        for (int j = 0; j < 8; ++j) {
            int gn = bn + tx * 8 + j;
            if (gn >= N) continue;
            float v = acc[i][j] + bs[j];
            if (relu) v = fmaxf(v, 0.0f);
            C[(size_t)gm * N + gn] = v;
        }
    }
}

// ---------------------------------------------------------------------------
// Launch
// Inputs (metadata order): x[int32 S*B], emb[f32 VOCAB*E], W1[f32 H1*600],
// b1[f32 H1], W2[f32 H2*H1], b2[f32 H2], W_out[f32 C*H2], b_out[f32 C]
// Output: f32 [B, C]
// ---------------------------------------------------------------------------
extern "C" void kernel_launch(void* const* d_in, const int* in_sizes, int n_in,
                              void* d_out, int out_size) {
    const int*   x     = (const int*)d_in[0];
    const float* emb   = (const float*)d_in[1];
    const float* W1    = (const float*)d_in[2];
    const float* b1    = (const float*)d_in[3];
    const float* W2    = (const float*)d_in[4];
    const float* b2    = (const float*)d_in[5];
    const float* W_out = (const float*)d_in[6];
    const float* b_out = (const float*)d_in[7];
    float* out = (float*)d_out;

    float* feat; cudaGetSymbolAddress((void**)&feat, g_feat);
    float* h1;   cudaGetSymbolAddress((void**)&h1, g_h1);
    float* h2;   cudaGetSymbolAddress((void**)&h2, g_h2);

    // Stage 1: features
    feat_kernel<<<BATCH, 320>>>(x, emb, feat);

    // Stage 2: MLP
    {
        dim3 grid((H1DIM + 127) / 128, (BATCH + 127) / 128);
        sgemm_nt_bias_act<<<grid, 256>>>(feat, W1, b1, h1, BATCH, H1DIM, FEAT, 1);
    }
    {
        dim3 grid((H2DIM + 127) / 128, (BATCH + 127) / 128);
        sgemm_nt_bias_act<<<grid, 256>>>(h1, W2, b2, h2, BATCH, H2DIM, H1DIM, 1);
    }
    {
        dim3 grid((NCLASS + 127) / 128, (BATCH + 127) / 128);
        sgemm_nt_bias_act<<<grid, 256>>>(h2, W_out, b_out, out, BATCH, NCLASS, H2DIM, 0);
    }
}

// round 4
// speedup vs baseline: 2.9793x; 2.9793x over previous
#include <cuda_runtime.h>
#include <cuda_bf16.h>
#include <cstdint>

// Problem constants
#define SEQ 128
#define BATCH 8192
#define EMB 300
#define H1DIM 2048
#define H2DIM 2048
#define NCLASS 1221
#define PAD_ID 1

#define K1PAD 640      // 600 padded to multiple of 64
#define NOPAD 1280     // 1221 padded to multiple of 128

// ---------------------------------------------------------------------------
// Scratch (static device globals)
// ---------------------------------------------------------------------------
__device__ __nv_bfloat16 g_feat_hi[(size_t)BATCH * K1PAD];
__device__ __nv_bfloat16 g_feat_lo[(size_t)BATCH * K1PAD];
__device__ __nv_bfloat16 g_w1h[(size_t)H1DIM * K1PAD];
__device__ __nv_bfloat16 g_w1l[(size_t)H1DIM * K1PAD];
__device__ __nv_bfloat16 g_w2h[(size_t)H2DIM * H1DIM];
__device__ __nv_bfloat16 g_w2l[(size_t)H2DIM * H1DIM];
__device__ __nv_bfloat16 g_woh[(size_t)NOPAD * H2DIM];
__device__ __nv_bfloat16 g_wol[(size_t)NOPAD * H2DIM];
__device__ __nv_bfloat16 g_h1h[(size_t)BATCH * H1DIM];
__device__ __nv_bfloat16 g_h1l[(size_t)BATCH * H1DIM];
__device__ __nv_bfloat16 g_h2h[(size_t)BATCH * H2DIM];
__device__ __nv_bfloat16 g_h2l[(size_t)BATCH * H2DIM];

// ---------------------------------------------------------------------------
// PTX helpers (baseline ISA only: cp.async / ldmatrix / mma.sync — no tcgen05)
// ---------------------------------------------------------------------------
__device__ __forceinline__ uint32_t smem_u32(const void* p) {
    uint32_t a;
    asm("{ .reg .u64 t; cvta.to.shared.u64 t, %1; cvt.u32.u64 %0, t; }" : "=r"(a) : "l"(p));
    return a;
}
__device__ __forceinline__ void cpa16(uint32_t s, const void* g) {
    asm volatile("cp.async.cg.shared.global [%0], [%1], 16;" :: "r"(s), "l"(g));
}
__device__ __forceinline__ void cpa_commit() {
    asm volatile("cp.async.commit_group;" ::: "memory");
}
template <int N>
__device__ __forceinline__ void cpa_wait() {
    asm volatile("cp.async.wait_group %0;" :: "n"(N) : "memory");
}
__device__ __forceinline__ void ldm_x4(uint32_t* r, uint32_t addr) {
    asm volatile("ldmatrix.sync.aligned.m8n8.x4.shared.b16 {%0,%1,%2,%3}, [%4];"
                 : "=r"(r[0]), "=r"(r[1]), "=r"(r[2]), "=r"(r[3]) : "r"(addr));
}
__device__ __forceinline__ void mma_16816(float* c, const uint32_t* a, uint32_t b0, uint32_t b1) {
    asm volatile(
        "mma.sync.aligned.m16n8k16.row.col.f32.bf16.bf16.f32 "
        "{%0,%1,%2,%3}, {%4,%5,%6,%7}, {%8,%9}, {%0,%1,%2,%3};"
        : "+f"(c[0]), "+f"(c[1]), "+f"(c[2]), "+f"(c[3])
        : "r"(a[0]), "r"(a[1]), "r"(a[2]), "r"(a[3]), "r"(b0), "r"(b1));
}

// SMEM: 2 stages x 4 tiles (Ahi, Alo, Bhi, Blo), each tile 128 rows x 64 bf16
// = 128B/row with SW128 swizzle (chunk ^= row&7).
#define TILE_BYTES 16384
#define STAGE_BYTES (4 * TILE_BYTES)          // 64 KB
#define SMEM_TOTAL (2 * STAGE_BYTES)          // 128 KB

__device__ __forceinline__ uint32_t swz(uint32_t base, int r, int cb16) {
    // cb16: byte column, multiple of 16
    return base + r * 128 + ((((cb16 >> 4) ^ (r & 7)) << 4));
}

// ---------------------------------------------------------------------------
// Stage 1: features -> split bf16, padded [BATCH, K1PAD]
// ---------------------------------------------------------------------------
__global__ __launch_bounds__(320) void feat_kernel(const int* __restrict__ x,
                                                   const float* __restrict__ emb,
                                                   __nv_bfloat16* __restrict__ fhi,
                                                   __nv_bfloat16* __restrict__ flo) {
    __shared__ int toks[SEQ];
    __shared__ int s_last;
    const int b = blockIdx.x;
    const int tid = threadIdx.x;

    if (tid < SEQ) toks[tid] = x[(size_t)tid * BATCH + b];
    __syncthreads();
    if (tid == 0) {
        int last = SEQ - 1;
        for (int s = SEQ - 1; s >= 0; --s)
            if (toks[s] != PAD_ID) { last = s; break; }
        s_last = last;
    }
    __syncthreads();
    const int last = s_last;
    const float inv = 1.0f / (float)(last + 1);
    const size_t rowoff = (size_t)b * K1PAD;

    const int e = tid;
    if (e < EMB) {
        float acc = 0.0f;
        int s = 0;
        for (; s + 3 <= last; s += 4) {
            float v0 = emb[(size_t)toks[s + 0] * EMB + e];
            float v1 = emb[(size_t)toks[s + 1] * EMB + e];
            float v2 = emb[(size_t)toks[s + 2] * EMB + e];
            float v3 = emb[(size_t)toks[s + 3] * EMB + e];
            acc += (v0 + v1) + (v2 + v3);
        }
        for (; s <= last; ++s) acc += emb[(size_t)toks[s] * EMB + e];

        float v_first = emb[(size_t)toks[0] * EMB + e];
        float v_mean = acc * inv;

        __nv_bfloat16 h0 = __float2bfloat16(v_first);
        fhi[rowoff + e] = h0;
        flo[rowoff + e] = __float2bfloat16(v_first - __bfloat162float(h0));
        __nv_bfloat16 h1 = __float2bfloat16(v_mean);
        fhi[rowoff + EMB + e] = h1;
        flo[rowoff + EMB + e] = __float2bfloat16(v_mean - __bfloat162float(h1));
    }
    if (tid < K1PAD - 2 * EMB) {   // zero pad cols 600..639
        fhi[rowoff + 2 * EMB + tid] = __float2bfloat16(0.0f);
        flo[rowoff + 2 * EMB + tid] = __float2bfloat16(0.0f);
    }
}

// ---------------------------------------------------------------------------
// Weight conversion: fp32 [srcRows, K] -> split bf16 [dstRows, Kpad] (0-padded)
// ---------------------------------------------------------------------------
__global__ __launch_bounds__(256) void conv_split(const float* __restrict__ src,
                                                  __nv_bfloat16* __restrict__ hi,
                                                  __nv_bfloat16* __restrict__ lo,
                                                  int srcRows, int dstRows, int K, int Kpad) {
    int idx = blockIdx.x * 256 + threadIdx.x;
    if (idx >= dstRows * Kpad) return;
    int r = idx / Kpad, c = idx - r * Kpad;
    float v = (r < srcRows && c < K) ? src[(size_t)r * K + c] : 0.0f;
    __nv_bfloat16 h = __float2bfloat16(v);
    hi[idx] = h;
    lo[idx] = __float2bfloat16(v - __bfloat162float(h));
}

// ---------------------------------------------------------------------------
// HMMA bf16x3 GEMM: C[M,N] = act(A @ B^T + bias)
//   A = Ahi+Alo [M, Kpad], B = Bhi+Blo [Npad, Kpad], K-major, padded.
//   acc += Ah*Bh + Ah*Bl + Al*Bh  (fp32 accumulators in registers)
// CTA tile 128x128, BK=64, 256 threads, 8 warps (4m x 2n), warp tile 32x64.
// mode 1: ReLU, write split bf16 (outHi/outLo); mode 0: fp32 out, N-guarded.
// ---------------------------------------------------------------------------
__global__ __launch_bounds__(256, 1) void gemm_hmma_x3(
        const __nv_bfloat16* __restrict__ Ahi, const __nv_bfloat16* __restrict__ Alo,
        const __nv_bfloat16* __restrict__ Bhi, const __nv_bfloat16* __restrict__ Blo,
        const float* __restrict__ bias,
        float* __restrict__ outF,
        __nv_bfloat16* __restrict__ outHi, __nv_bfloat16* __restrict__ outLo,
        int Kpad, int Nreal, int outStride, int mode) {
    extern __shared__ __align__(1024) char smem[];
    const uint32_t sb = smem_u32(smem);
    const int tid = threadIdx.x;
    const int lane = tid & 31;
    const int wid = tid >> 5;
    const int warp_m = wid >> 1;        // 0..3
    const int warp_n = wid & 1;         // 0..1
    const int bn = blockIdx.x * 128;
    const int bm = blockIdx.y * 128;

    const __nv_bfloat16* srcs[4] = {Ahi, Alo, Bhi, Blo};

    // ---- stage loader: 4 tiles x 1024 chunks of 16B, 16 cp.async per thread
    auto load_stage = [&](int c, int st) {
        const int k0 = c << 6;
        const uint32_t stb = sb + st * STAGE_BYTES;
#pragma unroll
        for (int t = 0; t < 4; ++t) {
            const __nv_bfloat16* src = srcs[t];
            const int rbase = (t < 2) ? bm : bn;
#pragma unroll
            for (int i = 0; i < 4; ++i) {
                int idx = tid + i * 256;          // 0..1023
                int r = idx >> 3;                 // 0..127
                int ch = idx & 7;                 // 16B chunk
                const void* g = src + (size_t)(rbase + r) * Kpad + k0 + ch * 8;
                cpa16(stb + t * TILE_BYTES + r * 128 + (((ch ^ (r & 7)) << 4)), g);
            }
        }
    };

    float acc[2][8][4];
#pragma unroll
    for (int a = 0; a < 2; ++a)
#pragma unroll
        for (int n = 0; n < 8; ++n)
#pragma unroll
            for (int q = 0; q < 4; ++q) acc[a][n][q] = 0.0f;

    const int nch = Kpad >> 6;
    load_stage(0, 0);
    cpa_commit();

    for (int c = 0; c < nch; ++c) {
        const int st = c & 1;
        if (c + 1 < nch) {
            load_stage(c + 1, st ^ 1);
            cpa_commit();
            cpa_wait<1>();
        } else {
            cpa_wait<0>();
        }
        __syncthreads();

        const uint32_t stb = sb + st * STAGE_BYTES;
#pragma unroll
        for (int s = 0; s < 4; ++s) {           // 4 k-steps of 16
            uint32_t ah[2][4], al[2][4], bh[4][4], bl[4][4];
#pragma unroll
            for (int a = 0; a < 2; ++a) {
                int r = warp_m * 32 + a * 16 + (lane & 15);
                int cb = s * 32 + ((lane >> 4) << 4);
                uint32_t ad = swz(stb, r, cb);
                ldm_x4(ah[a], ad);
                ldm_x4(al[a], ad + TILE_BYTES);
            }
#pragma unroll
            for (int p = 0; p < 4; ++p) {       // 4 n-pairs (16 n rows each)
                int r = warp_n * 64 + p * 16 + (lane & 7) + (((lane >> 4) & 1) << 3);
                int cb = s * 32 + (((lane >> 3) & 1) << 4);
                uint32_t bd = swz(stb + 2 * TILE_BYTES, r, cb);
                ldm_x4(bh[p], bd);
                ldm_x4(bl[p], bd + TILE_BYTES);
            }
#pragma unroll
            for (int a = 0; a < 2; ++a)
#pragma unroll
                for (int p = 0; p < 4; ++p) {
                    mma_16816(acc[a][2 * p],     ah[a], bh[p][0], bh[p][1]);
                    mma_16816(acc[a][2 * p + 1], ah[a], bh[p][2], bh[p][3]);
                    mma_16816(acc[a][2 * p],     ah[a], bl[p][0], bl[p][1]);
                    mma_16816(acc[a][2 * p + 1], ah[a], bl[p][2], bl[p][3]);
                    mma_16816(acc[a][2 * p],     al[a], bh[p][0], bh[p][1]);
                    mma_16816(acc[a][2 * p + 1], al[a], bh[p][2], bh[p][3]);
                }
        }
        __syncthreads();
    }

    // ---------------- Epilogue (register-resident) ----------------
    // acc[a][na] maps: rows = bm + warp_m*32 + a*16 + lane/4 (+8 for q>=2),
    //                  cols = bn + warp_n*64 + (na>>1)*16 + (na&1)*8 + 2*(lane&3) (+1)
    if (mode == 1) {
#pragma unroll
        for (int na = 0; na < 8; ++na) {
            const int gn = bn + warp_n * 64 + (na >> 1) * 16 + (na & 1) * 8 + 2 * (lane & 3);
            const float bv0 = bias[gn], bv1 = bias[gn + 1];
#pragma unroll
            for (int a = 0; a < 2; ++a) {
                const float* cr = acc[a][na];
                const int r0 = bm + warp_m * 32 + a * 16 + (lane >> 2);
#pragma unroll
                for (int h = 0; h < 2; ++h) {   // q pairs: (0,1) row r0, (2,3) row r0+8
                    const int gm = r0 + h * 8;
                    float v0 = fmaxf(cr[2 * h] + bv0, 0.0f);
                    float v1 = fmaxf(cr[2 * h + 1] + bv1, 0.0f);
                    __nv_bfloat16 h0 = __float2bfloat16(v0);
                    __nv_bfloat16 h1 = __float2bfloat16(v1);
                    __nv_bfloat16 l0 = __float2bfloat16(v0 - __bfloat162float(h0));
                    __nv_bfloat16 l1 = __float2bfloat16(v1 - __bfloat162float(h1));
                    uint32_t hp = (uint32_t)__bfloat16_as_ushort(h0) |
                                  ((uint32_t)__bfloat16_as_ushort(h1) << 16);
                    uint32_t lp = (uint32_t)__bfloat16_as_ushort(l0) |
                                  ((uint32_t)__bfloat16_as_ushort(l1) << 16);
                    size_t go = (size_t)gm * outStride + gn;
                    *reinterpret_cast<uint32_t*>(outHi + go) = hp;
                    *reinterpret_cast<uint32_t*>(outLo + go) = lp;
                }
            }
        }
    } else {
#pragma unroll
        for (int na = 0; na < 8; ++na) {
            const int gn = bn + warp_n * 64 + (na >> 1) * 16 + (na & 1) * 8 + 2 * (lane & 3);
            const float bv0 = (gn < Nreal) ? bias[gn] : 0.0f;
            const float bv1 = (gn + 1 < Nreal) ? bias[gn + 1] : 0.0f;
#pragma unroll
            for (int a = 0; a < 2; ++a) {
                const float* cr = acc[a][na];
                const int r0 = bm + warp_m * 32 + a * 16 + (lane >> 2);
#pragma unroll
                for (int h = 0; h < 2; ++h) {
                    const int gm = r0 + h * 8;
                    if (gn < Nreal)
                        outF[(size_t)gm * outStride + gn] = cr[2 * h] + bv0;
                    if (gn + 1 < Nreal)
                        outF[(size_t)gm * outStride + gn + 1] = cr[2 * h + 1] + bv1;
                }
            }
        }
    }
}

// ---------------------------------------------------------------------------
// Launch
// ---------------------------------------------------------------------------
extern "C" void kernel_launch(void* const* d_in, const int* in_sizes, int n_in,
                              void* d_out, int out_size) {
    const int*   x     = (const int*)d_in[0];
    const float* emb   = (const float*)d_in[1];
    const float* W1    = (const float*)d_in[2];
    const float* b1    = (const float*)d_in[3];
    const float* W2    = (const float*)d_in[4];
    const float* b2    = (const float*)d_in[5];
    const float* W_out = (const float*)d_in[6];
    const float* b_out = (const float*)d_in[7];
    float* out = (float*)d_out;

    __nv_bfloat16 *fh, *fl, *w1h, *w1l, *w2h, *w2l, *woh, *wol, *h1h, *h1l, *h2h, *h2l;
    cudaGetSymbolAddress((void**)&fh,  g_feat_hi);
    cudaGetSymbolAddress((void**)&fl,  g_feat_lo);
    cudaGetSymbolAddress((void**)&w1h, g_w1h);
    cudaGetSymbolAddress((void**)&w1l, g_w1l);
    cudaGetSymbolAddress((void**)&w2h, g_w2h);
    cudaGetSymbolAddress((void**)&w2l, g_w2l);
    cudaGetSymbolAddress((void**)&woh, g_woh);
    cudaGetSymbolAddress((void**)&wol, g_wol);
    cudaGetSymbolAddress((void**)&h1h, g_h1h);
    cudaGetSymbolAddress((void**)&h1l, g_h1l);
    cudaGetSymbolAddress((void**)&h2h, g_h2h);
    cudaGetSymbolAddress((void**)&h2l, g_h2l);

    cudaFuncSetAttribute(gemm_hmma_x3, cudaFuncAttributeMaxDynamicSharedMemorySize, SMEM_TOTAL);

    // Weight conversions + features (independent)
    {
        int n = H1DIM * K1PAD;
        conv_split<<<(n + 255) / 256, 256>>>(W1, w1h, w1l, H1DIM, H1DIM, 600, K1PAD);
    }
    {
        int n = H2DIM * H1DIM;
        conv_split<<<(n + 255) / 256, 256>>>(W2, w2h, w2l, H2DIM, H2DIM, H1DIM, H1DIM);
    }
    {
        int n = NOPAD * H2DIM;
        conv_split<<<(n + 255) / 256, 256>>>(W_out, woh, wol, NCLASS, NOPAD, H2DIM, H2DIM);
    }
    feat_kernel<<<BATCH, 320>>>(x, emb, fh, fl);

    // GEMM1: [8192,640] x [2048,640]^T -> h1 (ReLU, split bf16)
    {
        dim3 grid(H1DIM / 128, BATCH / 128);
        gemm_hmma_x3<<<grid, 256, SMEM_TOTAL>>>(fh, fl, w1h, w1l, b1,
                                                nullptr, h1h, h1l,
                                                K1PAD, H1DIM, H1DIM, 1);
    }
    // GEMM2: [8192,2048] x [2048,2048]^T -> h2 (ReLU, split bf16)
    {
        dim3 grid(H2DIM / 128, BATCH / 128);
        gemm_hmma_x3<<<grid, 256, SMEM_TOTAL>>>(h1h, h1l, w2h, w2l, b2,
                                                nullptr, h2h, h2l,
                                                H1DIM, H2DIM, H2DIM, 1);
    }
    // GEMM3: [8192,2048] x [1280,2048]^T -> out fp32 [8192,1221]
    {
        dim3 grid(NOPAD / 128, BATCH / 128);
        gemm_hmma_x3<<<grid, 256, SMEM_TOTAL>>>(h2h, h2l, woh, wol, b_out,
                                                out, nullptr, nullptr,
                                                H2DIM, NCLASS, NCLASS, 0);
    }
}

// round 5
// speedup vs baseline: 3.1826x; 1.0682x over previous
#include <cuda_runtime.h>
#include <cuda_bf16.h>
#include <cstdint>

// Problem constants
#define SEQ 128
#define BATCH 8192
#define EMB 300
#define H1DIM 2048
#define H2DIM 2048
#define NCLASS 1221
#define PAD_ID 1

#define K1PAD 640      // 600 padded to multiple of 64
#define NOPAD 1280     // 1221 padded to multiple of 128

// ---------------------------------------------------------------------------
// Scratch (static device globals)
// ---------------------------------------------------------------------------
__device__ __nv_bfloat16 g_feat_hi[(size_t)BATCH * K1PAD];
__device__ __nv_bfloat16 g_feat_lo[(size_t)BATCH * K1PAD];
__device__ __nv_bfloat16 g_w1h[(size_t)H1DIM * K1PAD];
__device__ __nv_bfloat16 g_w1l[(size_t)H1DIM * K1PAD];
__device__ __nv_bfloat16 g_w2h[(size_t)H2DIM * H1DIM];
__device__ __nv_bfloat16 g_w2l[(size_t)H2DIM * H1DIM];
__device__ __nv_bfloat16 g_woh[(size_t)NOPAD * H2DIM];
__device__ __nv_bfloat16 g_wol[(size_t)NOPAD * H2DIM];
__device__ __nv_bfloat16 g_h1h[(size_t)BATCH * H1DIM];
__device__ __nv_bfloat16 g_h1l[(size_t)BATCH * H1DIM];
__device__ __nv_bfloat16 g_h2h[(size_t)BATCH * H2DIM];
__device__ __nv_bfloat16 g_h2l[(size_t)BATCH * H2DIM];

// ---------------------------------------------------------------------------
// PTX helpers (baseline ISA only: cp.async / ldmatrix / mma.sync)
// ---------------------------------------------------------------------------
__device__ __forceinline__ uint32_t smem_u32(const void* p) {
    uint32_t a;
    asm("{ .reg .u64 t; cvta.to.shared.u64 t, %1; cvt.u32.u64 %0, t; }" : "=r"(a) : "l"(p));
    return a;
}
__device__ __forceinline__ void cpa16(uint32_t s, const void* g) {
    asm volatile("cp.async.cg.shared.global [%0], [%1], 16;" :: "r"(s), "l"(g));
}
__device__ __forceinline__ void cpa_commit() {
    asm volatile("cp.async.commit_group;" ::: "memory");
}
template <int N>
__device__ __forceinline__ void cpa_wait() {
    asm volatile("cp.async.wait_group %0;" :: "n"(N) : "memory");
}
__device__ __forceinline__ void ldm_x4(uint32_t* r, uint32_t addr) {
    asm volatile("ldmatrix.sync.aligned.m8n8.x4.shared.b16 {%0,%1,%2,%3}, [%4];"
                 : "=r"(r[0]), "=r"(r[1]), "=r"(r[2]), "=r"(r[3]) : "r"(addr));
}
__device__ __forceinline__ void mma_16816(float* c, const uint32_t* a, uint32_t b0, uint32_t b1) {
    asm volatile(
        "mma.sync.aligned.m16n8k16.row.col.f32.bf16.bf16.f32 "
        "{%0,%1,%2,%3}, {%4,%5,%6,%7}, {%8,%9}, {%0,%1,%2,%3};"
        : "+f"(c[0]), "+f"(c[1]), "+f"(c[2]), "+f"(c[3])
        : "r"(a[0]), "r"(a[1]), "r"(a[2]), "r"(a[3]), "r"(b0), "r"(b1));
}

// SMEM: 3 stages x 4 tiles (Ahi, Alo, Bhi, Blo), each tile 128 rows x 64 bf16
// = 128B/row with SW128 swizzle (chunk ^= row&7).
#define TILE_BYTES 16384
#define STAGE_BYTES (4 * TILE_BYTES)          // 64 KB
#define NSTAGE 3
#define SMEM_TOTAL (NSTAGE * STAGE_BYTES)     // 192 KB

__device__ __forceinline__ uint32_t swz(uint32_t base, int r, int cb16) {
    return base + r * 128 + ((((cb16 >> 4) ^ (r & 7)) << 4));
}

// Split-pack helpers: float pair -> packed bf16 hi / lo words
__device__ __forceinline__ uint32_t pack_hi2(float a, float b) {
    __nv_bfloat16 ha = __float2bfloat16(a), hb = __float2bfloat16(b);
    return (uint32_t)__bfloat16_as_ushort(ha) | ((uint32_t)__bfloat16_as_ushort(hb) << 16);
}
__device__ __forceinline__ uint32_t pack_lo2(float a, float b) {
    __nv_bfloat16 ha = __float2bfloat16(a), hb = __float2bfloat16(b);
    __nv_bfloat16 la = __float2bfloat16(a - __bfloat162float(ha));
    __nv_bfloat16 lb = __float2bfloat16(b - __bfloat162float(hb));
    return (uint32_t)__bfloat16_as_ushort(la) | ((uint32_t)__bfloat16_as_ushort(lb) << 16);
}

// ---------------------------------------------------------------------------
// Stage 1: features -> split bf16, padded [BATCH, K1PAD]
// One block per sentence, 96 threads; threads 0..74 each own a float4 chunk
// (75 x 4 = 300 dims), loads are LDG.128.
// ---------------------------------------------------------------------------
__global__ __launch_bounds__(96) void feat_kernel(const int* __restrict__ x,
                                                  const float* __restrict__ emb,
                                                  __nv_bfloat16* __restrict__ fhi,
                                                  __nv_bfloat16* __restrict__ flo) {
    __shared__ int toks[SEQ];
    __shared__ int s_last;
    const int b = blockIdx.x;
    const int tid = threadIdx.x;

    for (int s = tid; s < SEQ; s += 96) toks[s] = x[(size_t)s * BATCH + b];
    __syncthreads();
    if (tid == 0) {
        int last = SEQ - 1;
        for (int s = SEQ - 1; s >= 0; --s)
            if (toks[s] != PAD_ID) { last = s; break; }
        s_last = last;
    }
    __syncthreads();
    const int last = s_last;
    const float inv = 1.0f / (float)(last + 1);
    const size_t rowoff = (size_t)b * K1PAD;

    if (tid < 75) {
        const int c4 = tid * 4;
        float4 acc = make_float4(0.f, 0.f, 0.f, 0.f);
        int s = 0;
        for (; s + 3 <= last; s += 4) {
            float4 v0 = *reinterpret_cast<const float4*>(emb + (size_t)toks[s + 0] * EMB + c4);
            float4 v1 = *reinterpret_cast<const float4*>(emb + (size_t)toks[s + 1] * EMB + c4);
            float4 v2 = *reinterpret_cast<const float4*>(emb + (size_t)toks[s + 2] * EMB + c4);
            float4 v3 = *reinterpret_cast<const float4*>(emb + (size_t)toks[s + 3] * EMB + c4);
            acc.x += (v0.x + v1.x) + (v2.x + v3.x);
            acc.y += (v0.y + v1.y) + (v2.y + v3.y);
            acc.z += (v0.z + v1.z) + (v2.z + v3.z);
            acc.w += (v0.w + v1.w) + (v2.w + v3.w);
        }
        for (; s <= last; ++s) {
            float4 v = *reinterpret_cast<const float4*>(emb + (size_t)toks[s] * EMB + c4);
            acc.x += v.x; acc.y += v.y; acc.z += v.z; acc.w += v.w;
        }

        float4 vf = *reinterpret_cast<const float4*>(emb + (size_t)toks[0] * EMB + c4);
        float4 vm = make_float4(acc.x * inv, acc.y * inv, acc.z * inv, acc.w * inv);

        uint2 fh = make_uint2(pack_hi2(vf.x, vf.y), pack_hi2(vf.z, vf.w));
        uint2 fl = make_uint2(pack_lo2(vf.x, vf.y), pack_lo2(vf.z, vf.w));
        uint2 mh = make_uint2(pack_hi2(vm.x, vm.y), pack_hi2(vm.z, vm.w));
        uint2 ml = make_uint2(pack_lo2(vm.x, vm.y), pack_lo2(vm.z, vm.w));

        *reinterpret_cast<uint2*>(fhi + rowoff + c4) = fh;
        *reinterpret_cast<uint2*>(flo + rowoff + c4) = fl;
        *reinterpret_cast<uint2*>(fhi + rowoff + EMB + c4) = mh;
        *reinterpret_cast<uint2*>(flo + rowoff + EMB + c4) = ml;
    } else if (tid < 85) {
        // zero pad cols 600..639 (10 chunks of 4)
        const int e = 600 + (tid - 75) * 4;
        uint2 z = make_uint2(0u, 0u);
        *reinterpret_cast<uint2*>(fhi + rowoff + e) = z;
        *reinterpret_cast<uint2*>(flo + rowoff + e) = z;
    }
}

// ---------------------------------------------------------------------------
// Weight conversion: fp32 [srcRows, K] -> split bf16 [dstRows, Kpad] (0-padded)
// ---------------------------------------------------------------------------
__global__ __launch_bounds__(256) void conv_split(const float* __restrict__ src,
                                                  __nv_bfloat16* __restrict__ hi,
                                                  __nv_bfloat16* __restrict__ lo,
                                                  int srcRows, int dstRows, int K, int Kpad) {
    int idx = blockIdx.x * 256 + threadIdx.x;
    if (idx >= dstRows * Kpad) return;
    int r = idx / Kpad, c = idx - r * Kpad;
    float v = (r < srcRows && c < K) ? src[(size_t)r * K + c] : 0.0f;
    __nv_bfloat16 h = __float2bfloat16(v);
    hi[idx] = h;
    lo[idx] = __float2bfloat16(v - __bfloat162float(h));
}

// ---------------------------------------------------------------------------
// HMMA bf16x3 GEMM: C[M,N] = act(A @ B^T + bias)
//   acc += Ah*Bh + Ah*Bl + Al*Bh  (fp32 accumulators in registers)
// CTA tile 128x128, BK=64, 256 threads, 8 warps (4m x 2n), warp tile 32x64.
// 3-stage cp.async pipeline.
// mode 1: ReLU, write split bf16 (outHi/outLo); mode 0: fp32 out, N-guarded.
// ---------------------------------------------------------------------------
__global__ __launch_bounds__(256, 1) void gemm_hmma_x3(
        const __nv_bfloat16* __restrict__ Ahi, const __nv_bfloat16* __restrict__ Alo,
        const __nv_bfloat16* __restrict__ Bhi, const __nv_bfloat16* __restrict__ Blo,
        const float* __restrict__ bias,
        float* __restrict__ outF,
        __nv_bfloat16* __restrict__ outHi, __nv_bfloat16* __restrict__ outLo,
        int Kpad, int Nreal, int outStride, int mode) {
    extern __shared__ __align__(1024) char smem[];
    const uint32_t sb = smem_u32(smem);
    const int tid = threadIdx.x;
    const int lane = tid & 31;
    const int wid = tid >> 5;
    const int warp_m = wid >> 1;        // 0..3
    const int warp_n = wid & 1;         // 0..1
    const int bn = blockIdx.x * 128;
    const int bm = blockIdx.y * 128;

    const __nv_bfloat16* srcs[4] = {Ahi, Alo, Bhi, Blo};

    auto load_stage = [&](int c, int st) {
        const int k0 = c << 6;
        const uint32_t stb = sb + st * STAGE_BYTES;
#pragma unroll
        for (int t = 0; t < 4; ++t) {
            const __nv_bfloat16* src = srcs[t];
            const int rbase = (t < 2) ? bm : bn;
#pragma unroll
            for (int i = 0; i < 4; ++i) {
                int idx = tid + i * 256;          // 0..1023
                int r = idx >> 3;                 // 0..127
                int ch = idx & 7;                 // 16B chunk
                const void* g = src + (size_t)(rbase + r) * Kpad + k0 + ch * 8;
                cpa16(stb + t * TILE_BYTES + r * 128 + (((ch ^ (r & 7)) << 4)), g);
            }
        }
    };

    float acc[2][8][4];
#pragma unroll
    for (int a = 0; a < 2; ++a)
#pragma unroll
        for (int n = 0; n < 8; ++n)
#pragma unroll
            for (int q = 0; q < 4; ++q) acc[a][n][q] = 0.0f;

    const int nch = Kpad >> 6;

    // Prologue: two stages in flight; guarantee stage 0 resident.
    load_stage(0, 0); cpa_commit();
    if (nch > 1) { load_stage(1, 1); cpa_commit(); }
    cpa_wait<1>();
    __syncthreads();

    for (int c = 0; c < nch; ++c) {
        const int st = c % NSTAGE;
        // Issue loads for c+2 into the buffer freed at iteration c-1.
        if (c + 2 < nch) { load_stage(c + 2, (c + 2) % NSTAGE); cpa_commit(); }

        const uint32_t stb = sb + st * STAGE_BYTES;
#pragma unroll
        for (int s = 0; s < 4; ++s) {           // 4 k-steps of 16
            uint32_t ah[2][4], al[2][4], bh[4][4], bl[4][4];
#pragma unroll
            for (int a = 0; a < 2; ++a) {
                int r = warp_m * 32 + a * 16 + (lane & 15);
                int cb = s * 32 + ((lane >> 4) << 4);
                uint32_t ad = swz(stb, r, cb);
                ldm_x4(ah[a], ad);
                ldm_x4(al[a], ad + TILE_BYTES);
            }
#pragma unroll
            for (int p = 0; p < 4; ++p) {       // 4 n-pairs (16 n rows each)
                int r = warp_n * 64 + p * 16 + (lane & 7) + (((lane >> 4) & 1) << 3);
                int cb = s * 32 + (((lane >> 3) & 1) << 4);
                uint32_t bd = swz(stb + 2 * TILE_BYTES, r, cb);
                ldm_x4(bh[p], bd);
                ldm_x4(bl[p], bd + TILE_BYTES);
            }
#pragma unroll
            for (int a = 0; a < 2; ++a)
#pragma unroll
                for (int p = 0; p < 4; ++p) {
                    mma_16816(acc[a][2 * p],     ah[a], bh[p][0], bh[p][1]);
                    mma_16816(acc[a][2 * p + 1], ah[a], bh[p][2], bh[p][3]);
                    mma_16816(acc[a][2 * p],     ah[a], bl[p][0], bl[p][1]);
                    mma_16816(acc[a][2 * p + 1], ah[a], bl[p][2], bl[p][3]);
                    mma_16816(acc[a][2 * p],     al[a], bh[p][0], bh[p][1]);
                    mma_16816(acc[a][2 * p + 1], al[a], bh[p][2], bh[p][3]);
                }
        }

        // Ensure next stage resident; free this stage for reuse at c+3.
        cpa_wait<1>();
        __syncthreads();
    }

    // ---------------- Epilogue (register-resident) ----------------
    if (mode == 1) {
#pragma unroll
        for (int na = 0; na < 8; ++na) {
            const int gn = bn + warp_n * 64 + (na >> 1) * 16 + (na & 1) * 8 + 2 * (lane & 3);
            const float bv0 = bias[gn], bv1 = bias[gn + 1];
#pragma unroll
            for (int a = 0; a < 2; ++a) {
                const float* cr = acc[a][na];
                const int r0 = bm + warp_m * 32 + a * 16 + (lane >> 2);
#pragma unroll
                for (int h = 0; h < 2; ++h) {
                    const int gm = r0 + h * 8;
                    float v0 = fmaxf(cr[2 * h] + bv0, 0.0f);
                    float v1 = fmaxf(cr[2 * h + 1] + bv1, 0.0f);
                    size_t go = (size_t)gm * outStride + gn;
                    *reinterpret_cast<uint32_t*>(outHi + go) = pack_hi2(v0, v1);
                    *reinterpret_cast<uint32_t*>(outLo + go) = pack_lo2(v0, v1);
                }
            }
        }
    } else {
#pragma unroll
        for (int na = 0; na < 8; ++na) {
            const int gn = bn + warp_n * 64 + (na >> 1) * 16 + (na & 1) * 8 + 2 * (lane & 3);
            const float bv0 = (gn < Nreal) ? bias[gn] : 0.0f;
            const float bv1 = (gn + 1 < Nreal) ? bias[gn + 1] : 0.0f;
#pragma unroll
            for (int a = 0; a < 2; ++a) {
                const float* cr = acc[a][na];
                const int r0 = bm + warp_m * 32 + a * 16 + (lane >> 2);
#pragma unroll
                for (int h = 0; h < 2; ++h) {
                    const int gm = r0 + h * 8;
                    if (gn < Nreal)
                        outF[(size_t)gm * outStride + gn] = cr[2 * h] + bv0;
                    if (gn + 1 < Nreal)
                        outF[(size_t)gm * outStride + gn + 1] = cr[2 * h + 1] + bv1;
                }
            }
        }
    }
}

// ---------------------------------------------------------------------------
// Launch
// ---------------------------------------------------------------------------
extern "C" void kernel_launch(void* const* d_in, const int* in_sizes, int n_in,
                              void* d_out, int out_size) {
    const int*   x     = (const int*)d_in[0];
    const float* emb   = (const float*)d_in[1];
    const float* W1    = (const float*)d_in[2];
    const float* b1    = (const float*)d_in[3];
    const float* W2    = (const float*)d_in[4];
    const float* b2    = (const float*)d_in[5];
    const float* W_out = (const float*)d_in[6];
    const float* b_out = (const float*)d_in[7];
    float* out = (float*)d_out;

    __nv_bfloat16 *fh, *fl, *w1h, *w1l, *w2h, *w2l, *woh, *wol, *h1h, *h1l, *h2h, *h2l;
    cudaGetSymbolAddress((void**)&fh,  g_feat_hi);
    cudaGetSymbolAddress((void**)&fl,  g_feat_lo);
    cudaGetSymbolAddress((void**)&w1h, g_w1h);
    cudaGetSymbolAddress((void**)&w1l, g_w1l);
    cudaGetSymbolAddress((void**)&w2h, g_w2h);
    cudaGetSymbolAddress((void**)&w2l, g_w2l);
    cudaGetSymbolAddress((void**)&woh, g_woh);
    cudaGetSymbolAddress((void**)&wol, g_wol);
    cudaGetSymbolAddress((void**)&h1h, g_h1h);
    cudaGetSymbolAddress((void**)&h1l, g_h1l);
    cudaGetSymbolAddress((void**)&h2h, g_h2h);
    cudaGetSymbolAddress((void**)&h2l, g_h2l);

    cudaFuncSetAttribute(gemm_hmma_x3, cudaFuncAttributeMaxDynamicSharedMemorySize, SMEM_TOTAL);

    // Weight conversions + features (independent)
    {
        int n = H1DIM * K1PAD;
        conv_split<<<(n + 255) / 256, 256>>>(W1, w1h, w1l, H1DIM, H1DIM, 600, K1PAD);
    }
    {
        int n = H2DIM * H1DIM;
        conv_split<<<(n + 255) / 256, 256>>>(W2, w2h, w2l, H2DIM, H2DIM, H1DIM, H1DIM);
    }
    {
        int n = NOPAD * H2DIM;
        conv_split<<<(n + 255) / 256, 256>>>(W_out, woh, wol, NCLASS, NOPAD, H2DIM, H2DIM);
    }
    feat_kernel<<<BATCH, 96>>>(x, emb, fh, fl);

    // GEMM1: [8192,640] x [2048,640]^T -> h1 (ReLU, split bf16)
    {
        dim3 grid(H1DIM / 128, BATCH / 128);
        gemm_hmma_x3<<<grid, 256, SMEM_TOTAL>>>(fh, fl, w1h, w1l, b1,
                                                nullptr, h1h, h1l,
                                                K1PAD, H1DIM, H1DIM, 1);
    }
    // GEMM2: [8192,2048] x [2048,2048]^T -> h2 (ReLU, split bf16)
    {
        dim3 grid(H2DIM / 128, BATCH / 128);
        gemm_hmma_x3<<<grid, 256, SMEM_TOTAL>>>(h1h, h1l, w2h, w2l, b2,
                                                nullptr, h2h, h2l,
                                                H1DIM, H2DIM, H2DIM, 1);
    }
    // GEMM3: [8192,2048] x [1280,2048]^T -> out fp32 [8192,1221]
    {
        dim3 grid(NOPAD / 128, BATCH / 128);
        gemm_hmma_x3<<<grid, 256, SMEM_TOTAL>>>(h2h, h2l, woh, wol, b_out,
                                                out, nullptr, nullptr,
                                                H2DIM, NCLASS, NCLASS, 0);
    }
}